// round 13
// baseline (speedup 1.0000x reference)
#include <cuda_runtime.h>
#include <cstdint>

#define NN   100000
#define EE   1600000
#define EP   1700000   // EE + NN self loops
#define HH   4
#define CC   32
#define HC   128
#define EDD  16
#define NBLK ((NN + 255) / 256)

// ---------------- scratch: accessed ONLY by direct symbol in device code ----
static __device__ int   g_degi[NN];
static __device__ int   g_bsum[NBLK];
static __device__ int   g_rowptr[NN + 1];
static __device__ int   g_cursor[NN];
static __device__ int   g_csrc[EP];
static __device__ int   g_ceid[EP];
static __device__ float g_meanattr[(size_t)NN * EDD];
static __device__ float g_feat1[(size_t)NN * HC];
static __device__ float g_h1[(size_t)NN * HC];
static __device__ float g_feat2[(size_t)NN * CC];
static __device__ float g_als1[(size_t)NN * HH];
static __device__ float g_ald1[(size_t)NN * HH];
static __device__ float g_als2[NN];
static __device__ float g_ald2[NN];
static __device__ float g_eb1[(size_t)EP * HH];
static __device__ float g_eb2[EP];
static __device__ float g_m2[NN];
static __device__ float g_z2[NN];
static __device__ float g_ve1[EDD * HH];
static __device__ float g_ve2[EDD];
static __device__ float g_alpha_scratch[EP];

__device__ __forceinline__ float elu1f(float v) { return v > 0.f ? v : expm1f(v); }

__device__ __forceinline__ void load_edge(const int* __restrict__ ei, int e,
                                          int& src, int& dst) {
    if (e >= EE) { src = e - EE; dst = src; return; }
    src = ei[e]; dst = ei[EE + e];
}

// ---------------- CSR build ---------------------------------------------------
__global__ __launch_bounds__(256) void k_degzero() {
    int i = blockIdx.x * 256 + threadIdx.x;
    if (i < NN) g_degi[i] = 0;
}

__global__ __launch_bounds__(256) void k_deg(const int* __restrict__ ei) {
    int e = blockIdx.x * 256 + threadIdx.x;
    if (e >= EE) return;
    atomicAdd(&g_degi[ei[EE + e]], 1);
}

__global__ __launch_bounds__(256) void k_scan1() {
    int t = threadIdx.x, b = blockIdx.x;
    int idx = b * 256 + t;
    int val = (idx < NN) ? (g_degi[idx] + 1) : 0;   // +1 self loop
    __shared__ int s[256];
    s[t] = val;
    __syncthreads();
    for (int off = 1; off < 256; off <<= 1) {
        int v = (t >= off) ? s[t - off] : 0;
        __syncthreads();
        s[t] += v;
        __syncthreads();
    }
    if (idx < NN) g_rowptr[idx] = s[t] - val;       // local exclusive prefix
    if (t == 255) g_bsum[b] = s[255];
}

__global__ void k_scan2() {
    int t = threadIdx.x;   // 512 threads
    __shared__ int s[512];
    int v = (t < NBLK) ? g_bsum[t] : 0;
    s[t] = v;
    __syncthreads();
    for (int off = 1; off < 512; off <<= 1) {
        int u = (t >= off) ? s[t - off] : 0;
        __syncthreads();
        s[t] += u;
        __syncthreads();
    }
    if (t < NBLK) g_bsum[t] = s[t] - v;             // exclusive block offsets
}

__global__ __launch_bounds__(256) void k_scan3() {
    int idx = blockIdx.x * 256 + threadIdx.x;
    if (idx < NN) {
        int r = g_rowptr[idx] + g_bsum[blockIdx.x];
        g_rowptr[idx] = r;
        g_cursor[idx] = r;
    }
    if (idx == 0) g_rowptr[NN] = EP;
}

__global__ __launch_bounds__(256) void k_fill(const int* __restrict__ ei) {
    int e = blockIdx.x * 256 + threadIdx.x;
    if (e >= EP) return;
    int src, dst;
    load_edge(ei, e, src, dst);
    int pos = atomicAdd(&g_cursor[dst], 1);
    g_csrc[pos] = src;
    g_ceid[pos] = e;
}

// ---------------- small precompute -------------------------------------------
__global__ void k_ve(const float* __restrict__ W1e, const float* __restrict__ a1e,
                     const float* __restrict__ W2e, const float* __restrict__ a2e) {
    int t = threadIdx.x;
    if (t < EDD * HH) {
        int k = t / HH, h = t % HH;
        float s = 0.f;
        for (int c = 0; c < CC; c++) s += W1e[k * HC + h * CC + c] * a1e[h * CC + c];
        g_ve1[k * HH + h] = s;
    } else if (t < EDD * HH + EDD) {
        int k = t - EDD * HH;
        float s = 0.f;
        for (int c = 0; c < CC; c++) s += W2e[k * CC + c] * a2e[c];
        g_ve2[k] = s;
    }
}

// mean incoming edge attr per node (CSR, no atomics)
__global__ __launch_bounds__(256) void k_mean(const float* __restrict__ eattr) {
    int w = (blockIdx.x * 256 + threadIdx.x) >> 5;
    if (w >= NN) return;
    int lane = threadIdx.x & 31;
    if (lane >= EDD) return;
    int beg = g_rowptr[w], end = g_rowptr[w + 1];
    float s = 0.f;
    int cnt = 0;
    for (int i = beg; i < end; i++) {
        int e = g_ceid[i];
        if (e < EE) { s += eattr[(size_t)e * EDD + lane]; cnt++; }
    }
    g_meanattr[(size_t)w * EDD + lane] = s / fmaxf((float)cnt, 1.f);
}

// ---------------- layer 1 -----------------------------------------------------
// feat1 = x @ W1 (block per row), fused als1/ald1 (warp w == head w)
__global__ __launch_bounds__(128) void k_gemm1(const float* __restrict__ x,
                                               const float* __restrict__ W1,
                                               const float* __restrict__ a1s,
                                               const float* __restrict__ a1d) {
    __shared__ float xr[128];
    int n = blockIdx.x, t = threadIdx.x;
    xr[t] = x[(size_t)n * 128 + t];
    __syncthreads();
    float acc = 0.f;
    #pragma unroll 16
    for (int k = 0; k < 128; k++) acc += xr[k] * W1[k * 128 + t];
    g_feat1[(size_t)n * 128 + t] = acc;
    float ps = acc * a1s[t], pd = acc * a1d[t];
    for (int off = 16; off; off >>= 1) {
        ps += __shfl_down_sync(0xffffffffu, ps, off);
        pd += __shfl_down_sync(0xffffffffu, pd, off);
    }
    if ((t & 31) == 0) {
        int h = t >> 5;
        g_als1[(size_t)n * HH + h] = ps;
        g_ald1[(size_t)n * HH + h] = pd;
    }
}

__global__ __launch_bounds__(256) void k_logits1(const int* __restrict__ ei,
                                                 const float* __restrict__ eattr) {
    int e = blockIdx.x * 256 + threadIdx.x;
    if (e >= EP) return;
    int src, dst;
    load_edge(ei, e, src, dst);
    const float* attr = (e < EE) ? eattr + (size_t)e * EDD
                                 : g_meanattr + (size_t)(e - EE) * EDD;
    float a[EDD];
    #pragma unroll
    for (int k = 0; k < EDD; k++) a[k] = attr[k];
    #pragma unroll
    for (int h = 0; h < HH; h++) {
        float s = 0.f;
        #pragma unroll
        for (int k = 0; k < EDD; k++) s += a[k] * g_ve1[k * HH + h];
        float el = g_als1[(size_t)src * HH + h] + g_ald1[(size_t)dst * HH + h] + s;
        g_eb1[(size_t)e * HH + h] = el > 0.f ? el : 0.2f * el;
    }
}

// warp per node: exact segment softmax + gather + fused bias/ELU
__global__ __launch_bounds__(256) void k_node1(const float* __restrict__ b1) {
    int w = (blockIdx.x * 256 + threadIdx.x) >> 5;
    if (w >= NN) return;
    int lane = threadIdx.x & 31, head = lane >> 3;
    int beg = g_rowptr[w], end = g_rowptr[w + 1];
    float m = -1e30f;
    for (int i = beg; i < end; i++)
        m = fmaxf(m, g_eb1[(size_t)g_ceid[i] * HH + head]);
    float z = 0.f;
    for (int i = beg; i < end; i++)
        z += __expf(g_eb1[(size_t)g_ceid[i] * HH + head] - m);
    z = fmaxf(z, 1e-30f);
    float4 acc = make_float4(0.f, 0.f, 0.f, 0.f);
    for (int i = beg; i < end; i++) {
        int e = g_ceid[i], s = g_csrc[i];
        float al = __expf(g_eb1[(size_t)e * HH + head] - m) / z;
        float4 v = *(const float4*)(g_feat1 + (size_t)s * HC + lane * 4);
        acc.x += al * v.x; acc.y += al * v.y;
        acc.z += al * v.z; acc.w += al * v.w;
    }
    float4 bb = *(const float4*)(b1 + lane * 4);
    acc.x = elu1f(acc.x + bb.x);
    acc.y = elu1f(acc.y + bb.y);
    acc.z = elu1f(acc.z + bb.z);
    acc.w = elu1f(acc.w + bb.w);
    *(float4*)(g_h1 + (size_t)w * HC + lane * 4) = acc;
}

// ---------------- layer 2 -----------------------------------------------------
// feat2 = h1 @ W2 (warp per row), fused als2/ald2
__global__ __launch_bounds__(256) void k_gemm2(const float* __restrict__ W2,
                                               const float* __restrict__ a2s,
                                               const float* __restrict__ a2d) {
    __shared__ float xs[8][128];
    int wip = threadIdx.x >> 5, lane = threadIdx.x & 31;
    int n = blockIdx.x * 8 + wip;
    if (n >= NN) return;
    for (int q = 0; q < 4; q++)
        xs[wip][q * 32 + lane] = g_h1[(size_t)n * 128 + q * 32 + lane];
    __syncwarp();
    float acc = 0.f;
    #pragma unroll 16
    for (int k = 0; k < 128; k++) acc += xs[wip][k] * W2[k * 32 + lane];
    g_feat2[(size_t)n * 32 + lane] = acc;
    float ps = acc * a2s[lane], pd = acc * a2d[lane];
    for (int off = 16; off; off >>= 1) {
        ps += __shfl_down_sync(0xffffffffu, ps, off);
        pd += __shfl_down_sync(0xffffffffu, pd, off);
    }
    if (lane == 0) { g_als2[n] = ps; g_ald2[n] = pd; }
}

__global__ __launch_bounds__(256) void k_logits2(const int* __restrict__ ei,
                                                 const float* __restrict__ eattr) {
    int e = blockIdx.x * 256 + threadIdx.x;
    if (e >= EP) return;
    int src, dst;
    load_edge(ei, e, src, dst);
    const float* attr = (e < EE) ? eattr + (size_t)e * EDD
                                 : g_meanattr + (size_t)(e - EE) * EDD;
    float s = 0.f;
    #pragma unroll
    for (int k = 0; k < EDD; k++) s += attr[k] * g_ve2[k];
    float el = g_als2[src] + g_ald2[dst] + s;
    g_eb2[e] = el > 0.f ? el : 0.2f * el;
}

// warp per node (lane = feature): softmax + gather + fused bias/ELU -> h2 out
__global__ __launch_bounds__(256) void k_node2(const float* __restrict__ b2,
                                               float* __restrict__ h2out) {
    int w = (blockIdx.x * 256 + threadIdx.x) >> 5;
    if (w >= NN) return;
    int lane = threadIdx.x & 31;
    int beg = g_rowptr[w], end = g_rowptr[w + 1];
    float m = -1e30f;
    for (int i = beg; i < end; i++) m = fmaxf(m, g_eb2[g_ceid[i]]);
    float z = 0.f;
    for (int i = beg; i < end; i++) z += __expf(g_eb2[g_ceid[i]] - m);
    z = fmaxf(z, 1e-30f);
    float acc = 0.f;
    for (int i = beg; i < end; i++) {
        float al = __expf(g_eb2[g_ceid[i]] - m) / z;
        acc += al * g_feat2[(size_t)g_csrc[i] * CC + lane];
    }
    h2out[(size_t)w * CC + lane] = elu1f(acc + b2[lane]);
    if (lane == 0) { g_m2[w] = m; g_z2[w] = z; }
}

// ---------------- auxiliary outputs ------------------------------------------
__global__ __launch_bounds__(256) void k_alpha2(const int* __restrict__ ei,
                                                float* __restrict__ alpha_out) {
    int e = blockIdx.x * 256 + threadIdx.x;
    if (e >= EP) return;
    int src, dst;
    load_edge(ei, e, src, dst);
    alpha_out[e] = __expf(g_eb2[e] - g_m2[dst]) / g_z2[dst];
}

__global__ __launch_bounds__(256) void k_eiout(const int* __restrict__ ei,
                                               float* __restrict__ dout) {
    int e = blockIdx.x * 256 + threadIdx.x;
    if (e >= EP) return;
    int s, d;
    load_edge(ei, e, s, d);
    dout[e] = (float)s;
    dout[(size_t)EP + e] = (float)d;
}

// ---------------- launch -----------------------------------------------------
extern "C" void kernel_launch(void* const* d_in, const int* in_sizes, int n_in,
                              void* d_out, int out_size) {
    const float* x = nullptr; const int* ei = nullptr; const float* eatt = nullptr;
    const float* W1 = nullptr; const float* W1e = nullptr;
    const float* W2 = nullptr; const float* W2e = nullptr;
    const float* v128[4] = {}; int n128 = 0;
    const float* v32[4]  = {}; int n32 = 0;
    for (int i = 0; i < n_in; i++) {
        int s = in_sizes[i];
        const void* p = d_in[i];
        switch (s) {
            case NN * 128:  x    = (const float*)p; break;
            case 2 * EE:    ei   = (const int*)p;   break;
            case EE * EDD:  eatt = (const float*)p; break;
            case 128 * 128: W1   = (const float*)p; break;
            case EDD * 128: W1e  = (const float*)p; break;
            case 128 * 32:  W2   = (const float*)p; break;
            case EDD * 32:  W2e  = (const float*)p; break;
            case 128:       if (n128 < 4) v128[n128++] = (const float*)p; break;
            case 32:        if (n32  < 4) v32 [n32++]  = (const float*)p; break;
            default: break;
        }
    }
    const float* a1s = v128[0]; const float* a1d = v128[1];
    const float* a1e = v128[2]; const float* b1  = v128[3];
    const float* a2s = v32[0];  const float* a2d = v32[1];
    const float* a2e = v32[2];  const float* b2  = v32[3];
    float* out = (float*)d_out;

    const size_t S_H2 = (size_t)NN * CC;
    const size_t S_EI = (size_t)2 * EP;
    const size_t S_AL = (size_t)EP;
    size_t osz = (size_t)out_size;
    float* out_h2    = out;
    float* out_ei    = nullptr;
    float* out_alpha = nullptr;
    if (osz >= S_H2 + S_EI + S_AL)      { out_ei = out + S_H2; out_alpha = out + S_H2 + S_EI; }
    else if (osz >= S_H2 + S_EI)        { out_ei = out + S_H2; }
    else if (osz >= S_H2 + S_AL)        { out_alpha = out + S_H2; }
    float* alpha_sink = out_alpha;
    if (alpha_sink == nullptr) {
        void* p = nullptr;
        cudaGetSymbolAddress(&p, g_alpha_scratch);   // the ONLY legal way to get a
        alpha_sink = (float*)p;                      // __device__ symbol address on host
    }

    const int T = 256;
    // CSR build
    k_degzero<<<(NN + T - 1) / T, T>>>();
    k_deg<<<(EE + T - 1) / T, T>>>(ei);
    k_scan1<<<NBLK, T>>>();
    k_scan2<<<1, 512>>>();
    k_scan3<<<NBLK, T>>>();
    k_fill<<<(EP + T - 1) / T, T>>>(ei);
    k_ve<<<1, 128>>>(W1e, a1e, W2e, a2e);
    k_mean<<<(NN * 32 + T - 1) / T, T>>>(eatt);

    // layer 1
    k_gemm1<<<NN, 128>>>(x, W1, a1s, a1d);
    k_logits1<<<(EP + T - 1) / T, T>>>(ei, eatt);
    k_node1<<<(NN * 32 + T - 1) / T, T>>>(b1);

    // layer 2
    k_gemm2<<<(NN + 7) / 8, T>>>(W2, a2s, a2d);
    k_logits2<<<(EP + T - 1) / T, T>>>(ei, eatt);
    k_node2<<<(NN * 32 + T - 1) / T, T>>>(b2, out_h2);

    // auxiliary outputs
    k_alpha2<<<(EP + T - 1) / T, T>>>(ei, alpha_sink);
    if (out_ei != nullptr)
        k_eiout<<<(EP + T - 1) / T, T>>>(ei, out_ei);
}

// round 14
// speedup vs baseline: 1.3578x; 1.3578x over previous
#include <cuda_runtime.h>
#include <cstdint>

#define NN   100000
#define EE   1600000
#define EP   1700000   // EE + NN self loops
#define HH   4
#define CC   32
#define HC   128
#define EDD  16
#define NBLK ((NN + 255) / 256)

// ---------------- scratch: accessed ONLY by direct symbol in device code ----
static __device__ int   g_degi[NN];
static __device__ int   g_bsum[NBLK];
static __device__ int   g_rowptr[NN + 1];
static __device__ int   g_cursor[NN];
static __device__ int   g_csrc[EP];
static __device__ int   g_ceid[EP];
static __device__ __align__(16) float g_edot1[(size_t)EE * HH];  // eattr . ve1 per real edge
static __device__ float g_edot2[EE];                              // eattr . ve2 per real edge
static __device__ __align__(16) float g_sdot1[(size_t)NN * HH];  // self-loop edge dots (= mean)
static __device__ float g_sdot2[NN];
static __device__ __align__(16) float g_feat1[(size_t)NN * HC];
static __device__ __align__(16) float g_h1[(size_t)NN * HC];
static __device__ __align__(16) float g_feat2[(size_t)NN * CC];
static __device__ __align__(16) float g_als1[(size_t)NN * HH];
static __device__ __align__(16) float g_ald1[(size_t)NN * HH];
static __device__ float g_als2[NN];
static __device__ float g_ald2[NN];
static __device__ __align__(16) float g_eb1[(size_t)EP * HH];    // p = exp(lrelu(logit))
static __device__ float g_eb2[EP];                                // p2
static __device__ float g_z2[NN];
static __device__ float g_ve1[EDD * HH];
static __device__ float g_ve2[EDD];
static __device__ float g_alpha_scratch[EP];

__device__ __forceinline__ float elu1f(float v) { return v > 0.f ? v : expm1f(v); }
__device__ __forceinline__ float lrelu(float v) { return v > 0.f ? v : 0.2f * v; }

__device__ __forceinline__ void load_edge(const int* __restrict__ ei, int e,
                                          int& src, int& dst) {
    if (e >= EE) { src = e - EE; dst = src; return; }
    src = ei[e]; dst = ei[EE + e];
}

// ---------------- CSR build ---------------------------------------------------
__global__ __launch_bounds__(256) void k_degzero() {
    int i = blockIdx.x * 256 + threadIdx.x;
    if (i < NN) g_degi[i] = 0;
}

__global__ __launch_bounds__(256) void k_deg(const int* __restrict__ ei) {
    int e = blockIdx.x * 256 + threadIdx.x;
    if (e >= EE) return;
    atomicAdd(&g_degi[ei[EE + e]], 1);
}

__global__ __launch_bounds__(256) void k_scan1() {
    int t = threadIdx.x, b = blockIdx.x;
    int idx = b * 256 + t;
    int val = (idx < NN) ? (g_degi[idx] + 1) : 0;   // +1 self loop
    __shared__ int s[256];
    s[t] = val;
    __syncthreads();
    for (int off = 1; off < 256; off <<= 1) {
        int v = (t >= off) ? s[t - off] : 0;
        __syncthreads();
        s[t] += v;
        __syncthreads();
    }
    if (idx < NN) g_rowptr[idx] = s[t] - val;
    if (t == 255) g_bsum[b] = s[255];
}

__global__ void k_scan2() {
    int t = threadIdx.x;   // 512 threads
    __shared__ int s[512];
    int v = (t < NBLK) ? g_bsum[t] : 0;
    s[t] = v;
    __syncthreads();
    for (int off = 1; off < 512; off <<= 1) {
        int u = (t >= off) ? s[t - off] : 0;
        __syncthreads();
        s[t] += u;
        __syncthreads();
    }
    if (t < NBLK) g_bsum[t] = s[t] - v;
}

__global__ __launch_bounds__(256) void k_scan3() {
    int idx = blockIdx.x * 256 + threadIdx.x;
    if (idx < NN) {
        int r = g_rowptr[idx] + g_bsum[blockIdx.x];
        g_rowptr[idx] = r;
        g_cursor[idx] = r;
    }
    if (idx == 0) g_rowptr[NN] = EP;
}

__global__ __launch_bounds__(256) void k_fill(const int* __restrict__ ei) {
    int e = blockIdx.x * 256 + threadIdx.x;
    if (e >= EP) return;
    int src, dst;
    load_edge(ei, e, src, dst);
    int pos = atomicAdd(&g_cursor[dst], 1);
    g_csrc[pos] = src;
    g_ceid[pos] = e;
}

// ---------------- small precompute -------------------------------------------
__global__ void k_ve(const float* __restrict__ W1e, const float* __restrict__ a1e,
                     const float* __restrict__ W2e, const float* __restrict__ a2e) {
    int t = threadIdx.x;
    if (t < EDD * HH) {
        int k = t / HH, h = t % HH;
        float s = 0.f;
        for (int c = 0; c < CC; c++) s += W1e[k * HC + h * CC + c] * a1e[h * CC + c];
        g_ve1[k * HH + h] = s;
    } else if (t < EDD * HH + EDD) {
        int k = t - EDD * HH;
        float s = 0.f;
        for (int c = 0; c < CC; c++) s += W2e[k * CC + c] * a2e[c];
        g_ve2[k] = s;
    }
}

// one sequential pass over eattr: both layers' edge dots
__global__ __launch_bounds__(256) void k_edot(const float* __restrict__ eattr) {
    int e = blockIdx.x * 256 + threadIdx.x;
    if (e >= EE) return;
    const float4* ap = (const float4*)(eattr + (size_t)e * EDD);
    float a[EDD];
    #pragma unroll
    for (int q = 0; q < 4; q++) {
        float4 v = ap[q];
        a[q * 4 + 0] = v.x; a[q * 4 + 1] = v.y; a[q * 4 + 2] = v.z; a[q * 4 + 3] = v.w;
    }
    float4 d1 = make_float4(0.f, 0.f, 0.f, 0.f);
    float d2 = 0.f;
    #pragma unroll
    for (int k = 0; k < EDD; k++) {
        d1.x += a[k] * g_ve1[k * HH + 0];
        d1.y += a[k] * g_ve1[k * HH + 1];
        d1.z += a[k] * g_ve1[k * HH + 2];
        d1.w += a[k] * g_ve1[k * HH + 3];
        d2   += a[k] * g_ve2[k];
    }
    *(float4*)(g_edot1 + (size_t)e * HH) = d1;
    g_edot2[e] = d2;
}

// self-loop dots = segment mean of edge dots (dot is linear in attr)
__global__ __launch_bounds__(256) void k_sdot() {
    int w = (blockIdx.x * 256 + threadIdx.x) >> 5;
    if (w >= NN) return;
    int lane = threadIdx.x & 31;
    if (lane >= 5) return;
    int beg = g_rowptr[w], end = g_rowptr[w + 1];
    float inv = 1.f / fmaxf((float)(end - beg - 1), 1.f);   // real-edge count
    float s = 0.f;
    for (int i = beg; i < end; i++) {
        int e = g_ceid[i];
        if (e < EE)
            s += (lane < 4) ? g_edot1[(size_t)e * HH + lane] : g_edot2[e];
    }
    if (lane < 4) g_sdot1[(size_t)w * HH + lane] = s * inv;
    else          g_sdot2[w] = s * inv;
}

// ---------------- layer 1 -----------------------------------------------------
__global__ __launch_bounds__(128) void k_gemm1(const float* __restrict__ x,
                                               const float* __restrict__ W1,
                                               const float* __restrict__ a1s,
                                               const float* __restrict__ a1d) {
    __shared__ float xr[128];
    int n = blockIdx.x, t = threadIdx.x;
    xr[t] = x[(size_t)n * 128 + t];
    __syncthreads();
    float acc = 0.f;
    #pragma unroll 16
    for (int k = 0; k < 128; k++) acc += xr[k] * W1[k * 128 + t];
    g_feat1[(size_t)n * 128 + t] = acc;
    float ps = acc * a1s[t], pd = acc * a1d[t];
    for (int off = 16; off; off >>= 1) {
        ps += __shfl_down_sync(0xffffffffu, ps, off);
        pd += __shfl_down_sync(0xffffffffu, pd, off);
    }
    if ((t & 31) == 0) {
        int h = t >> 5;
        g_als1[(size_t)n * HH + h] = ps;
        g_ald1[(size_t)n * HH + h] = pd;
    }
}

// p1 = exp(lrelu(logit)) — shift-free softmax numerator
__global__ __launch_bounds__(256) void k_logits1(const int* __restrict__ ei) {
    int e = blockIdx.x * 256 + threadIdx.x;
    if (e >= EP) return;
    int src, dst;
    load_edge(ei, e, src, dst);
    float4 ed = (e < EE) ? *(const float4*)(g_edot1 + (size_t)e * HH)
                         : *(const float4*)(g_sdot1 + (size_t)(e - EE) * HH);
    float4 as = *(const float4*)(g_als1 + (size_t)src * HH);
    float4 ad = *(const float4*)(g_ald1 + (size_t)dst * HH);
    float4 p;
    p.x = __expf(lrelu(as.x + ad.x + ed.x));
    p.y = __expf(lrelu(as.y + ad.y + ed.y));
    p.z = __expf(lrelu(as.z + ad.z + ed.z));
    p.w = __expf(lrelu(as.w + ad.w + ed.w));
    *(float4*)(g_eb1 + (size_t)e * HH) = p;
}

// warp per node: single-pass weighted gather, normalize at end, fused bias/ELU
__global__ __launch_bounds__(256) void k_node1(const float* __restrict__ b1) {
    int w = (blockIdx.x * 256 + threadIdx.x) >> 5;
    if (w >= NN) return;
    int lane = threadIdx.x & 31, head = lane >> 3;
    int beg = g_rowptr[w], end = g_rowptr[w + 1];
    float z = 0.f;
    float4 acc = make_float4(0.f, 0.f, 0.f, 0.f);
    for (int i = beg; i < end; i++) {
        int e = g_ceid[i], s = g_csrc[i];
        float p = g_eb1[(size_t)e * HH + head];
        float4 v = *(const float4*)(g_feat1 + (size_t)s * HC + lane * 4);
        z += p;
        acc.x += p * v.x; acc.y += p * v.y;
        acc.z += p * v.z; acc.w += p * v.w;
    }
    float inv = 1.f / fmaxf(z, 1e-30f);
    float4 bb = *(const float4*)(b1 + lane * 4);
    acc.x = elu1f(acc.x * inv + bb.x);
    acc.y = elu1f(acc.y * inv + bb.y);
    acc.z = elu1f(acc.z * inv + bb.z);
    acc.w = elu1f(acc.w * inv + bb.w);
    *(float4*)(g_h1 + (size_t)w * HC + lane * 4) = acc;
}

// ---------------- layer 2 -----------------------------------------------------
__global__ __launch_bounds__(256) void k_gemm2(const float* __restrict__ W2,
                                               const float* __restrict__ a2s,
                                               const float* __restrict__ a2d) {
    __shared__ float xs[8][128];
    int wip = threadIdx.x >> 5, lane = threadIdx.x & 31;
    int n = blockIdx.x * 8 + wip;
    if (n >= NN) return;
    for (int q = 0; q < 4; q++)
        xs[wip][q * 32 + lane] = g_h1[(size_t)n * 128 + q * 32 + lane];
    __syncwarp();
    float acc = 0.f;
    #pragma unroll 16
    for (int k = 0; k < 128; k++) acc += xs[wip][k] * W2[k * 32 + lane];
    g_feat2[(size_t)n * 32 + lane] = acc;
    float ps = acc * a2s[lane], pd = acc * a2d[lane];
    for (int off = 16; off; off >>= 1) {
        ps += __shfl_down_sync(0xffffffffu, ps, off);
        pd += __shfl_down_sync(0xffffffffu, pd, off);
    }
    if (lane == 0) { g_als2[n] = ps; g_ald2[n] = pd; }
}

__global__ __launch_bounds__(256) void k_logits2(const int* __restrict__ ei) {
    int e = blockIdx.x * 256 + threadIdx.x;
    if (e >= EP) return;
    int src, dst;
    load_edge(ei, e, src, dst);
    float ed = (e < EE) ? g_edot2[e] : g_sdot2[e - EE];
    g_eb2[e] = __expf(lrelu(g_als2[src] + g_ald2[dst] + ed));
}

// warp per node (lane = feature): single pass, store z2 for alpha output
__global__ __launch_bounds__(256) void k_node2(const float* __restrict__ b2,
                                               float* __restrict__ h2out) {
    int w = (blockIdx.x * 256 + threadIdx.x) >> 5;
    if (w >= NN) return;
    int lane = threadIdx.x & 31;
    int beg = g_rowptr[w], end = g_rowptr[w + 1];
    float z = 0.f, acc = 0.f;
    for (int i = beg; i < end; i++) {
        float p = g_eb2[g_ceid[i]];
        z += p;
        acc += p * g_feat2[(size_t)g_csrc[i] * CC + lane];
    }
    z = fmaxf(z, 1e-30f);
    h2out[(size_t)w * CC + lane] = elu1f(acc / z + b2[lane]);
    if (lane == 0) g_z2[w] = z;
}

// ---------------- auxiliary outputs ------------------------------------------
__global__ __launch_bounds__(256) void k_alpha2(const int* __restrict__ ei,
                                                float* __restrict__ alpha_out) {
    int e = blockIdx.x * 256 + threadIdx.x;
    if (e >= EP) return;
    int src, dst;
    load_edge(ei, e, src, dst);
    alpha_out[e] = g_eb2[e] / g_z2[dst];
}

__global__ __launch_bounds__(256) void k_eiout(const int* __restrict__ ei,
                                               float* __restrict__ dout) {
    int e = blockIdx.x * 256 + threadIdx.x;
    if (e >= EP) return;
    int s, d;
    load_edge(ei, e, s, d);
    dout[e] = (float)s;
    dout[(size_t)EP + e] = (float)d;
}

// ---------------- launch -----------------------------------------------------
extern "C" void kernel_launch(void* const* d_in, const int* in_sizes, int n_in,
                              void* d_out, int out_size) {
    const float* x = nullptr; const int* ei = nullptr; const float* eatt = nullptr;
    const float* W1 = nullptr; const float* W1e = nullptr;
    const float* W2 = nullptr; const float* W2e = nullptr;
    const float* v128[4] = {}; int n128 = 0;
    const float* v32[4]  = {}; int n32 = 0;
    for (int i = 0; i < n_in; i++) {
        int s = in_sizes[i];
        const void* p = d_in[i];
        switch (s) {
            case NN * 128:  x    = (const float*)p; break;
            case 2 * EE:    ei   = (const int*)p;   break;
            case EE * EDD:  eatt = (const float*)p; break;
            case 128 * 128: W1   = (const float*)p; break;
            case EDD * 128: W1e  = (const float*)p; break;
            case 128 * 32:  W2   = (const float*)p; break;
            case EDD * 32:  W2e  = (const float*)p; break;
            case 128:       if (n128 < 4) v128[n128++] = (const float*)p; break;
            case 32:        if (n32  < 4) v32 [n32++]  = (const float*)p; break;
            default: break;
        }
    }
    const float* a1s = v128[0]; const float* a1d = v128[1];
    const float* a1e = v128[2]; const float* b1  = v128[3];
    const float* a2s = v32[0];  const float* a2d = v32[1];
    const float* a2e = v32[2];  const float* b2  = v32[3];
    float* out = (float*)d_out;

    const size_t S_H2 = (size_t)NN * CC;
    const size_t S_EI = (size_t)2 * EP;
    const size_t S_AL = (size_t)EP;
    size_t osz = (size_t)out_size;
    float* out_h2    = out;
    float* out_ei    = nullptr;
    float* out_alpha = nullptr;
    if (osz >= S_H2 + S_EI + S_AL)      { out_ei = out + S_H2; out_alpha = out + S_H2 + S_EI; }
    else if (osz >= S_H2 + S_EI)        { out_ei = out + S_H2; }
    else if (osz >= S_H2 + S_AL)        { out_alpha = out + S_H2; }
    float* alpha_sink = out_alpha;
    if (alpha_sink == nullptr) {
        void* p = nullptr;
        cudaGetSymbolAddress(&p, g_alpha_scratch);
        alpha_sink = (float*)p;
    }

    const int T = 256;
    // CSR build
    k_degzero<<<(NN + T - 1) / T, T>>>();
    k_deg<<<(EE + T - 1) / T, T>>>(ei);
    k_scan1<<<NBLK, T>>>();
    k_scan2<<<1, 512>>>();
    k_scan3<<<NBLK, T>>>();
    k_fill<<<(EP + T - 1) / T, T>>>(ei);
    k_ve<<<1, 128>>>(W1e, a1e, W2e, a2e);
    k_edot<<<(EE + T - 1) / T, T>>>(eatt);
    k_sdot<<<(NN * 32 + T - 1) / T, T>>>();

    // layer 1
    k_gemm1<<<NN, 128>>>(x, W1, a1s, a1d);
    k_logits1<<<(EP + T - 1) / T, T>>>(ei);
    k_node1<<<(NN * 32 + T - 1) / T, T>>>(b1);

    // layer 2
    k_gemm2<<<(NN + 7) / 8, T>>>(W2, a2s, a2d);
    k_logits2<<<(EP + T - 1) / T, T>>>(ei);
    k_node2<<<(NN * 32 + T - 1) / T, T>>>(b2, out_h2);

    // auxiliary outputs
    k_alpha2<<<(EP + T - 1) / T, T>>>(ei, alpha_sink);
    if (out_ei != nullptr)
        k_eiout<<<(EP + T - 1) / T, T>>>(ei, out_ei);
}

// round 15
// speedup vs baseline: 1.7994x; 1.3252x over previous
#include <cuda_runtime.h>
#include <cstdint>

#define NN   100000
#define EE   1600000
#define EP   1700000   // EE + NN self loops
#define HH   4
#define CC   32
#define HC   128
#define EDD  16
#define NBLK ((NN + 255) / 256)

// ---------------- scratch: device symbols -----------------------------------
static __device__ int   g_degi[NN];
static __device__ int   g_bsum[NBLK];
static __device__ int   g_rowptr[NN + 1];
static __device__ int   g_cursor[NN];
static __device__ __align__(8) int2 g_cpack[EP];                 // (src, eid)
static __device__ __align__(16) float g_edot1[(size_t)EE * HH];
static __device__ float g_edot2[EE];
static __device__ __align__(16) float g_sdot1[(size_t)NN * HH];
static __device__ float g_sdot2[NN];
static __device__ __align__(16) float g_feat1[(size_t)NN * HC];
static __device__ __align__(16) float g_h1[(size_t)NN * HC];
static __device__ __align__(16) float g_feat2[(size_t)NN * CC];
static __device__ __align__(16) float g_als1[(size_t)NN * HH];
static __device__ __align__(16) float g_ald1[(size_t)NN * HH];
static __device__ float g_als2[NN];
static __device__ float g_ald2[NN];
static __device__ __align__(16) float g_eb1[(size_t)EP * HH];    // p1
static __device__ float g_eb2[EP];                                // p2
static __device__ float g_z2[NN];
static __device__ float g_ve1[EDD * HH];
static __device__ float g_ve2[EDD];
static __device__ float g_alpha_scratch[EP];

__device__ __forceinline__ float elu1f(float v) { return v > 0.f ? v : expm1f(v); }
__device__ __forceinline__ float lrelu(float v) { return v > 0.f ? v : 0.2f * v; }

__device__ __forceinline__ void load_edge(const int* __restrict__ ei, int e,
                                          int& src, int& dst) {
    if (e >= EE) { src = e - EE; dst = src; return; }
    src = ei[e]; dst = ei[EE + e];
}

// ---------------- CSR build ---------------------------------------------------
__global__ __launch_bounds__(256) void k_degzero() {
    int i = blockIdx.x * 256 + threadIdx.x;
    if (i < NN) g_degi[i] = 0;
}

__global__ __launch_bounds__(256) void k_deg(const int* __restrict__ ei) {
    int e = blockIdx.x * 256 + threadIdx.x;
    if (e >= EE) return;
    atomicAdd(&g_degi[ei[EE + e]], 1);
}

__global__ __launch_bounds__(256) void k_scan1() {
    int t = threadIdx.x, b = blockIdx.x;
    int idx = b * 256 + t;
    int val = (idx < NN) ? (g_degi[idx] + 1) : 0;
    __shared__ int s[256];
    s[t] = val;
    __syncthreads();
    for (int off = 1; off < 256; off <<= 1) {
        int v = (t >= off) ? s[t - off] : 0;
        __syncthreads();
        s[t] += v;
        __syncthreads();
    }
    if (idx < NN) g_rowptr[idx] = s[t] - val;
    if (t == 255) g_bsum[b] = s[255];
}

__global__ void k_scan2() {
    int t = threadIdx.x;   // 512
    __shared__ int s[512];
    int v = (t < NBLK) ? g_bsum[t] : 0;
    s[t] = v;
    __syncthreads();
    for (int off = 1; off < 512; off <<= 1) {
        int u = (t >= off) ? s[t - off] : 0;
        __syncthreads();
        s[t] += u;
        __syncthreads();
    }
    if (t < NBLK) g_bsum[t] = s[t] - v;
}

__global__ __launch_bounds__(256) void k_scan3() {
    int idx = blockIdx.x * 256 + threadIdx.x;
    if (idx < NN) {
        int r = g_rowptr[idx] + g_bsum[blockIdx.x];
        g_rowptr[idx] = r;
        g_cursor[idx] = r;
    }
    if (idx == 0) g_rowptr[NN] = EP;
}

__global__ __launch_bounds__(256) void k_fill(const int* __restrict__ ei) {
    int e = blockIdx.x * 256 + threadIdx.x;
    if (e >= EP) return;
    int src, dst;
    load_edge(ei, e, src, dst);
    int pos = atomicAdd(&g_cursor[dst], 1);
    g_cpack[pos] = make_int2(src, e);
}

// ---------------- precompute --------------------------------------------------
__global__ void k_ve(const float* __restrict__ W1e, const float* __restrict__ a1e,
                     const float* __restrict__ W2e, const float* __restrict__ a2e) {
    int t = threadIdx.x;
    if (t < EDD * HH) {
        int k = t / HH, h = t % HH;
        float s = 0.f;
        for (int c = 0; c < CC; c++) s += W1e[k * HC + h * CC + c] * a1e[h * CC + c];
        g_ve1[k * HH + h] = s;
    } else if (t < EDD * HH + EDD) {
        int k = t - EDD * HH;
        float s = 0.f;
        for (int c = 0; c < CC; c++) s += W2e[k * CC + c] * a2e[c];
        g_ve2[k] = s;
    }
}

__global__ __launch_bounds__(256) void k_edot(const float* __restrict__ eattr) {
    int e = blockIdx.x * 256 + threadIdx.x;
    if (e >= EE) return;
    const float4* ap = (const float4*)(eattr + (size_t)e * EDD);
    float a[EDD];
    #pragma unroll
    for (int q = 0; q < 4; q++) {
        float4 v = ap[q];
        a[q * 4 + 0] = v.x; a[q * 4 + 1] = v.y; a[q * 4 + 2] = v.z; a[q * 4 + 3] = v.w;
    }
    float4 d1 = make_float4(0.f, 0.f, 0.f, 0.f);
    float d2 = 0.f;
    #pragma unroll
    for (int k = 0; k < EDD; k++) {
        d1.x += a[k] * g_ve1[k * HH + 0];
        d1.y += a[k] * g_ve1[k * HH + 1];
        d1.z += a[k] * g_ve1[k * HH + 2];
        d1.w += a[k] * g_ve1[k * HH + 3];
        d2   += a[k] * g_ve2[k];
    }
    *(float4*)(g_edot1 + (size_t)e * HH) = d1;
    g_edot2[e] = d2;
}

// self-loop dots = segment mean (dot linear in attr)
__global__ __launch_bounds__(256) void k_sdot() {
    int w = (blockIdx.x * 256 + threadIdx.x) >> 5;
    if (w >= NN) return;
    int lane = threadIdx.x & 31;
    if (lane >= 5) return;
    int beg = g_rowptr[w], end = g_rowptr[w + 1];
    float inv = 1.f / fmaxf((float)(end - beg - 1), 1.f);
    float s = 0.f;
    for (int i = beg; i < end; i++) {
        int e = g_cpack[i].y;
        if (e < EE)
            s += (lane < 4) ? g_edot1[(size_t)e * HH + lane] : g_edot2[e];
    }
    if (lane < 4) g_sdot1[(size_t)w * HH + lane] = s * inv;
    else          g_sdot2[w] = s * inv;
}

// ---------------- tiled SGEMM (K = 128 fixed, N = BN) -------------------------
template <int BM, int BN, int BK, int TM, int TN>
__global__ __launch_bounds__((BM / TM) * (BN / TN)) void k_gemm_t(
    const float* __restrict__ A, const float* __restrict__ W,
    float* __restrict__ O, int M) {
    constexpr int THREADS = (BM / TM) * (BN / TN);
    constexpr int K = 128;
    __shared__ float As[BK][BM];
    __shared__ float Ws[BK][BN];
    int tid = threadIdx.x;
    int tcol = tid % (BN / TN);
    int trow = tid / (BN / TN);
    int m0 = blockIdx.x * BM;
    float acc[TM][TN] = {};
    for (int k0 = 0; k0 < K; k0 += BK) {
        #pragma unroll
        for (int q = 0; q < BM * BK / 4 / THREADS; q++) {
            int lin = (tid + q * THREADS) * 4;
            int r = lin / BK, c = lin % BK;
            float4 v = make_float4(0.f, 0.f, 0.f, 0.f);
            if (m0 + r < M) v = *(const float4*)(A + (size_t)(m0 + r) * K + k0 + c);
            As[c + 0][r] = v.x; As[c + 1][r] = v.y;
            As[c + 2][r] = v.z; As[c + 3][r] = v.w;
        }
        #pragma unroll
        for (int q = 0; q < BK * BN / 4 / THREADS; q++) {
            int lin = (tid + q * THREADS) * 4;
            int r = lin / BN, c = lin % BN;
            *(float4*)(&Ws[r][c]) = *(const float4*)(W + (size_t)(k0 + r) * BN + c);
        }
        __syncthreads();
        #pragma unroll
        for (int k = 0; k < BK; k++) {
            float a[TM], w[TN];
            #pragma unroll
            for (int i = 0; i < TM; i++) a[i] = As[k][trow * TM + i];
            #pragma unroll
            for (int j = 0; j < TN; j++) w[j] = Ws[k][tcol * TN + j];
            #pragma unroll
            for (int i = 0; i < TM; i++)
                #pragma unroll
                for (int j = 0; j < TN; j++)
                    acc[i][j] += a[i] * w[j];
        }
        __syncthreads();
    }
    #pragma unroll
    for (int i = 0; i < TM; i++) {
        int m = m0 + trow * TM + i;
        if (m < M) {
            #pragma unroll
            for (int j = 0; j < TN; j++)
                O[(size_t)m * BN + tcol * TN + j] = acc[i][j];
        }
    }
}

// ---------------- attention dot epilogues -------------------------------------
__global__ __launch_bounds__(256) void k_alsd1(const float* __restrict__ a1s,
                                               const float* __restrict__ a1d) {
    int w = (blockIdx.x * 256 + threadIdx.x) >> 5;
    if (w >= NN) return;
    int lane = threadIdx.x & 31;
    float4 f = *(const float4*)(g_feat1 + (size_t)w * HC + lane * 4);
    float4 s = *(const float4*)(a1s + lane * 4);
    float4 d = *(const float4*)(a1d + lane * 4);
    float ps = f.x * s.x + f.y * s.y + f.z * s.z + f.w * s.w;
    float pd = f.x * d.x + f.y * d.y + f.z * d.z + f.w * d.w;
    for (int off = 4; off; off >>= 1) {
        ps += __shfl_down_sync(0xffffffffu, ps, off, 8);
        pd += __shfl_down_sync(0xffffffffu, pd, off, 8);
    }
    if ((lane & 7) == 0) {
        int h = lane >> 3;
        g_als1[(size_t)w * HH + h] = ps;
        g_ald1[(size_t)w * HH + h] = pd;
    }
}

__global__ __launch_bounds__(256) void k_alsd2(const float* __restrict__ a2s,
                                               const float* __restrict__ a2d) {
    int w = (blockIdx.x * 256 + threadIdx.x) >> 5;
    if (w >= NN) return;
    int lane = threadIdx.x & 31;
    float f = g_feat2[(size_t)w * CC + lane];
    float ps = f * a2s[lane], pd = f * a2d[lane];
    for (int off = 16; off; off >>= 1) {
        ps += __shfl_down_sync(0xffffffffu, ps, off);
        pd += __shfl_down_sync(0xffffffffu, pd, off);
    }
    if (lane == 0) { g_als2[w] = ps; g_ald2[w] = pd; }
}

// ---------------- logits (shift-free p) ---------------------------------------
__global__ __launch_bounds__(256) void k_logits1(const int* __restrict__ ei) {
    int e = blockIdx.x * 256 + threadIdx.x;
    if (e >= EP) return;
    int src, dst;
    load_edge(ei, e, src, dst);
    float4 ed = (e < EE) ? *(const float4*)(g_edot1 + (size_t)e * HH)
                         : *(const float4*)(g_sdot1 + (size_t)(e - EE) * HH);
    float4 as = *(const float4*)(g_als1 + (size_t)src * HH);
    float4 ad = *(const float4*)(g_ald1 + (size_t)dst * HH);
    float4 p;
    p.x = __expf(lrelu(as.x + ad.x + ed.x));
    p.y = __expf(lrelu(as.y + ad.y + ed.y));
    p.z = __expf(lrelu(as.z + ad.z + ed.z));
    p.w = __expf(lrelu(as.w + ad.w + ed.w));
    *(float4*)(g_eb1 + (size_t)e * HH) = p;
}

__global__ __launch_bounds__(256) void k_logits2(const int* __restrict__ ei) {
    int e = blockIdx.x * 256 + threadIdx.x;
    if (e >= EP) return;
    int src, dst;
    load_edge(ei, e, src, dst);
    float ed = (e < EE) ? g_edot2[e] : g_sdot2[e - EE];
    g_eb2[e] = __expf(lrelu(g_als2[src] + g_ald2[dst] + ed));
}

// ---------------- node gathers -------------------------------------------------
__global__ __launch_bounds__(256) void k_node1(const float* __restrict__ b1) {
    int w = (blockIdx.x * 256 + threadIdx.x) >> 5;
    if (w >= NN) return;
    int lane = threadIdx.x & 31, head = lane >> 3;
    int beg = g_rowptr[w], end = g_rowptr[w + 1];
    float z = 0.f;
    float4 acc = make_float4(0.f, 0.f, 0.f, 0.f);
    for (int i = beg; i < end; i++) {
        int2 pk = g_cpack[i];
        float p = g_eb1[(size_t)pk.y * HH + head];
        float4 v = *(const float4*)(g_feat1 + (size_t)pk.x * HC + lane * 4);
        z += p;
        acc.x += p * v.x; acc.y += p * v.y;
        acc.z += p * v.z; acc.w += p * v.w;
    }
    float inv = 1.f / fmaxf(z, 1e-30f);
    float4 bb = *(const float4*)(b1 + lane * 4);
    acc.x = elu1f(acc.x * inv + bb.x);
    acc.y = elu1f(acc.y * inv + bb.y);
    acc.z = elu1f(acc.z * inv + bb.z);
    acc.w = elu1f(acc.w * inv + bb.w);
    *(float4*)(g_h1 + (size_t)w * HC + lane * 4) = acc;
}

__global__ __launch_bounds__(256) void k_node2(const float* __restrict__ b2,
                                               float* __restrict__ h2out) {
    int w = (blockIdx.x * 256 + threadIdx.x) >> 5;
    if (w >= NN) return;
    int lane = threadIdx.x & 31;
    int beg = g_rowptr[w], end = g_rowptr[w + 1];
    float z = 0.f, acc = 0.f;
    for (int i = beg; i < end; i++) {
        int2 pk = g_cpack[i];
        float p = g_eb2[pk.y];
        z += p;
        acc += p * g_feat2[(size_t)pk.x * CC + lane];
    }
    z = fmaxf(z, 1e-30f);
    h2out[(size_t)w * CC + lane] = elu1f(acc / z + b2[lane]);
    if (lane == 0) g_z2[w] = z;
}

// ---------------- merged auxiliary outputs ------------------------------------
__global__ __launch_bounds__(256) void k_aux(const int* __restrict__ ei,
                                             float* __restrict__ alpha_out,
                                             float* __restrict__ ei_out) {
    int e = blockIdx.x * 256 + threadIdx.x;
    if (e >= EP) return;
    int src, dst;
    load_edge(ei, e, src, dst);
    alpha_out[e] = g_eb2[e] / g_z2[dst];
    if (ei_out != nullptr) {
        ei_out[e] = (float)src;
        ei_out[(size_t)EP + e] = (float)dst;
    }
}

// ---------------- launch -------------------------------------------------------
extern "C" void kernel_launch(void* const* d_in, const int* in_sizes, int n_in,
                              void* d_out, int out_size) {
    const float* x = nullptr; const int* ei = nullptr; const float* eatt = nullptr;
    const float* W1 = nullptr; const float* W1e = nullptr;
    const float* W2 = nullptr; const float* W2e = nullptr;
    const float* v128[4] = {}; int n128 = 0;
    const float* v32[4]  = {}; int n32 = 0;
    for (int i = 0; i < n_in; i++) {
        int s = in_sizes[i];
        const void* p = d_in[i];
        switch (s) {
            case NN * 128:  x    = (const float*)p; break;
            case 2 * EE:    ei   = (const int*)p;   break;
            case EE * EDD:  eatt = (const float*)p; break;
            case 128 * 128: W1   = (const float*)p; break;
            case EDD * 128: W1e  = (const float*)p; break;
            case 128 * 32:  W2   = (const float*)p; break;
            case EDD * 32:  W2e  = (const float*)p; break;
            case 128:       if (n128 < 4) v128[n128++] = (const float*)p; break;
            case 32:        if (n32  < 4) v32 [n32++]  = (const float*)p; break;
            default: break;
        }
    }
    const float* a1s = v128[0]; const float* a1d = v128[1];
    const float* b1  = v128[3];
    const float* a2s = v32[0];  const float* a2d = v32[1];
    const float* b2  = v32[3];
    const float* a1e = v128[2]; const float* a2e = v32[2];
    float* out = (float*)d_out;

    const size_t S_H2 = (size_t)NN * CC;
    const size_t S_EI = (size_t)2 * EP;
    const size_t S_AL = (size_t)EP;
    size_t osz = (size_t)out_size;
    float* out_h2    = out;
    float* out_ei    = nullptr;
    float* out_alpha = nullptr;
    if (osz >= S_H2 + S_EI + S_AL)      { out_ei = out + S_H2; out_alpha = out + S_H2 + S_EI; }
    else if (osz >= S_H2 + S_EI)        { out_ei = out + S_H2; }
    else if (osz >= S_H2 + S_AL)        { out_alpha = out + S_H2; }
    float* alpha_sink = out_alpha;
    if (alpha_sink == nullptr) {
        void* p = nullptr;
        cudaGetSymbolAddress(&p, g_alpha_scratch);
        alpha_sink = (float*)p;
    }
    // symbol addresses for tiled GEMM operands (legal host-side symbol lookup)
    void *p_feat1 = nullptr, *p_h1 = nullptr, *p_feat2 = nullptr;
    cudaGetSymbolAddress(&p_feat1, g_feat1);
    cudaGetSymbolAddress(&p_h1,    g_h1);
    cudaGetSymbolAddress(&p_feat2, g_feat2);

    const int T = 256;
    // CSR build
    k_degzero<<<(NN + T - 1) / T, T>>>();
    k_deg<<<(EE + T - 1) / T, T>>>(ei);
    k_scan1<<<NBLK, T>>>();
    k_scan2<<<1, 512>>>();
    k_scan3<<<NBLK, T>>>();
    k_fill<<<(EP + T - 1) / T, T>>>(ei);
    k_ve<<<1, 128>>>(W1e, a1e, W2e, a2e);
    k_edot<<<(EE + T - 1) / T, T>>>(eatt);
    k_sdot<<<(NN * 32 + T - 1) / T, T>>>();

    // layer 1
    k_gemm_t<128, 128, 16, 8, 8><<<(NN + 127) / 128, 256>>>(x, W1, (float*)p_feat1, NN);
    k_alsd1<<<(NN * 32 + T - 1) / T, T>>>(a1s, a1d);
    k_logits1<<<(EP + T - 1) / T, T>>>(ei);
    k_node1<<<(NN * 32 + T - 1) / T, T>>>(b1);

    // layer 2
    k_gemm_t<128, 32, 32, 8, 2><<<(NN + 127) / 128, 256>>>((const float*)p_h1, W2, (float*)p_feat2, NN);
    k_alsd2<<<(NN * 32 + T - 1) / T, T>>>(a2s, a2d);
    k_logits2<<<(EP + T - 1) / T, T>>>(ei);
    k_node2<<<(NN * 32 + T - 1) / T, T>>>(b2, out_h2);

    // auxiliary outputs (merged)
    k_aux<<<(EP + T - 1) / T, T>>>(ei, alpha_sink, out_ei);
}